// round 3
// baseline (speedup 1.0000x reference)
#include <cuda_runtime.h>
#include <math.h>

#define BATCH 32
#define CIN   256
#define OHW   28
#define HW    784          // 28*28
#define IH    56
#define IHW   3136         // 56*56

// ---------------- scratch (static device arrays; no cudaMalloc) ----------------
__device__ float g_f1r [BATCH * CIN * HW];          // resized feature1  [b][c][q]
__device__ float g_f2r [BATCH * CIN * HW];          // resized feature2  [b][c][q]
__device__ float g_mpool[BATCH * HW];               // maxpooled mask    [b][q]
__device__ float g_scale[BATCH * HW];               // mask/||corr||     [b][q]
__device__ float g_corr [(size_t)BATCH * HW * HW];  // relu(corr)        [b][p][q]
__device__ float g_y2a  [BATCH * 192 * HW];
__device__ float g_y3a  [BATCH *  32 * HW];
__device__ float g_y    [BATCH * 512 * HW];         // concat buffer
__device__ float g_mean [512];
__device__ float g_inv  [512];

// ---------------- bilinear resize 56->28, align_corners=True ----------------
__global__ void resize_k(const float* __restrict__ f1, const float* __restrict__ f2) {
    int idx = blockIdx.x * blockDim.x + threadIdx.x;
    const int total = BATCH * CIN * HW;
    if (idx >= 2 * total) return;
    const float* src = (idx < total) ? f1 : f2;
    float* dst       = (idx < total) ? g_f1r : g_f2r;
    int i  = (idx < total) ? idx : idx - total;
    int q  = i % HW;
    int bc = i / HW;
    int oy = q / OHW, ox = q % OHW;
    const float step = 55.0f / 27.0f;
    float fy = oy * step, fx = ox * step;
    int y0 = (int)floorf(fy); if (y0 > IH - 1) y0 = IH - 1;
    int x0 = (int)floorf(fx); if (x0 > IH - 1) x0 = IH - 1;
    int y1 = min(y0 + 1, IH - 1);
    int x1 = min(x0 + 1, IH - 1);
    float wy = fy - (float)y0;
    float wx = fx - (float)x0;
    const float* p = src + (size_t)bc * IHW;
    float v00 = p[y0 * IH + x0], v01 = p[y0 * IH + x1];
    float v10 = p[y1 * IH + x0], v11 = p[y1 * IH + x1];
    float r0 = v00 * (1.0f - wy) + v10 * wy;   // y-interp first (matches ref order)
    float r1 = v01 * (1.0f - wy) + v11 * wy;
    dst[i] = r0 * (1.0f - wx) + r1 * wx;
}

// ---------------- mask maxpool 2x2 s2 ----------------
__global__ void mpool_k(const float* __restrict__ mask) {
    int idx = blockIdx.x * blockDim.x + threadIdx.x;
    if (idx >= BATCH * HW) return;
    int b = idx / HW, q = idx % HW;
    int y = q / OHW, x = q % OHW;
    const float* p = mask + (size_t)b * IHW;
    float m0 = p[(2*y)   * IH + 2*x], m1 = p[(2*y)   * IH + 2*x + 1];
    float m2 = p[(2*y+1) * IH + 2*x], m3 = p[(2*y+1) * IH + 2*x + 1];
    g_mpool[idx] = fmaxf(fmaxf(m0, m1), fmaxf(m2, m3));
}

// =====================================================================
// 128x128x8 double-buffered SGEMM, 256 threads, 8x8 micro-tile.
// C[b][m][n] = relu( epiScale?[b][n] * (sum_k A.B) + bias?[m] )
// MODE: 0 = plain B[k][n] (row stride N)
//       3/5 = conv im2col decode (pad = MODE/2) from B[c][28][28]
//       9 = B[k][n] = max over 3x3 nbhd of corr[k][q']*scale[q'] (W4 branch)
// WA: true -> A is weights [m][k] (stride sAm=K); false -> A[k][m] (stride sAk)
// =====================================================================
template <int MODE, bool WA>
__global__ __launch_bounds__(256, 2)
void gemm_k(const float* __restrict__ A, const float* __restrict__ Bm,
            float* __restrict__ C,
            int M, int N, int K,
            long aB, long bB, long cB,
            int sAk, int sAm,
            const float* __restrict__ scale,   // epi scale (MODE!=9) or pool scale (MODE==9)
            const float* __restrict__ bias,
            int cStride)
{
    const int b = blockIdx.z;
    const float* Ab = A  + (size_t)b * aB;
    const float* Bb = Bm + (size_t)b * bB;
    float*       Cb = C  + (size_t)b * cB;
    const float* scb = scale ? scale + (size_t)b * HW : (const float*)0;

    const int m0 = blockIdx.y * 128;
    const int n0 = blockIdx.x * 128;

    __shared__ float As[2][8][128];
    __shared__ float Bs[2][8][128];

    const int tid = threadIdx.x;
    const int tx  = tid & 15;
    const int ty  = tid >> 4;

    // loader indices
    const int a_k  = tid >> 5;            // act mode: k row 0..7
    const int a_m4 = (tid & 31) * 4;      // act mode: m col
    const int aw_m = tid >> 1;            // weight mode: m 0..127
    const int aw_k = (tid & 1) * 4;       // weight mode: k offset 0 or 4
    const int b_k  = tid >> 5;            // B: k row 0..7
    const int b_n4 = (tid & 31) * 4;      // B: n col

    float4 avr, bvr;
    const float4 f4z = make_float4(0.f, 0.f, 0.f, 0.f);

#define LOAD_A(K0)                                                              \
    {                                                                           \
        avr = f4z;                                                              \
        if (WA) {                                                               \
            if (m0 + aw_m < M)                                                  \
                avr = *(const float4*)&Ab[(size_t)(m0 + aw_m) * sAm + (K0) + aw_k]; \
        } else {                                                                \
            if (m0 + a_m4 < M)                                                  \
                avr = *(const float4*)&Ab[(size_t)((K0) + a_k) * sAk + m0 + a_m4]; \
        }                                                                       \
    }

#define STORE_A(BUF)                                                            \
    {                                                                           \
        if (WA) {                                                               \
            As[BUF][aw_k + 0][aw_m] = avr.x;                                    \
            As[BUF][aw_k + 1][aw_m] = avr.y;                                    \
            As[BUF][aw_k + 2][aw_m] = avr.z;                                    \
            As[BUF][aw_k + 3][aw_m] = avr.w;                                    \
        } else {                                                                \
            *(float4*)&As[BUF][a_k][a_m4] = avr;                                \
        }                                                                       \
    }

#define LOAD_B(K0)                                                              \
    {                                                                           \
        if (MODE == 0) {                                                        \
            bvr = f4z;                                                          \
            if (n0 + b_n4 < N)                                                  \
                bvr = *(const float4*)&Bb[(size_t)((K0) + b_k) * N + n0 + b_n4];\
        } else if (MODE == 9) {                                                 \
            const int gk = (K0) + b_k;                                          \
            const float* row = Bb + (size_t)gk * HW;                            \
            float vv[4];                                                        \
            _Pragma("unroll")                                                   \
            for (int j = 0; j < 4; j++) {                                       \
                int gn = n0 + b_n4 + j;                                         \
                float mx = 0.0f;                                                \
                if (gn < N) {                                                   \
                    int y = gn / OHW, x = gn % OHW;                             \
                    mx = -INFINITY;                                             \
                    _Pragma("unroll")                                           \
                    for (int dy = -1; dy <= 1; dy++) {                          \
                        int iy = y + dy;                                        \
                        if (iy < 0 || iy >= OHW) continue;                      \
                        _Pragma("unroll")                                       \
                        for (int dx = -1; dx <= 1; dx++) {                      \
                            int ix = x + dx;                                    \
                            if (ix < 0 || ix >= OHW) continue;                  \
                            int qq = iy * OHW + ix;                             \
                            mx = fmaxf(mx, row[qq] * scb[qq]);                  \
                        }                                                       \
                    }                                                           \
                }                                                               \
                vv[j] = mx;                                                     \
            }                                                                   \
            bvr = make_float4(vv[0], vv[1], vv[2], vv[3]);                      \
        } else {                                                                \
            const int kk2 = MODE * MODE;                                        \
            const int pad = MODE / 2;                                           \
            const int gk = (K0) + b_k;                                          \
            const int c  = gk / kk2;                                            \
            const int r  = gk % kk2;                                            \
            const int ky = r / MODE, kx = r % MODE;                             \
            float vv[4];                                                        \
            _Pragma("unroll")                                                   \
            for (int j = 0; j < 4; j++) {                                       \
                int gn = n0 + b_n4 + j;                                         \
                float v = 0.0f;                                                 \
                if (gn < N) {                                                   \
                    int y = gn / OHW + ky - pad;                                \
                    int x = gn % OHW + kx - pad;                                \
                    if (y >= 0 && y < OHW && x >= 0 && x < OHW)                 \
                        v = Bb[c * HW + y * OHW + x];                           \
                }                                                               \
                vv[j] = v;                                                      \
            }                                                                   \
            bvr = make_float4(vv[0], vv[1], vv[2], vv[3]);                      \
        }                                                                       \
    }

#define STORE_B(BUF) { *(float4*)&Bs[BUF][b_k][b_n4] = bvr; }

    float acc[8][8];
#pragma unroll
    for (int i = 0; i < 8; i++)
#pragma unroll
        for (int j = 0; j < 8; j++) acc[i][j] = 0.0f;

    const int nt = K >> 3;

    LOAD_A(0); LOAD_B(0);
    STORE_A(0); STORE_B(0);
    __syncthreads();

    for (int t = 0; t < nt; t++) {
        const int buf = t & 1;
        if (t + 1 < nt) { LOAD_A((t + 1) * 8); LOAD_B((t + 1) * 8); }
#pragma unroll
        for (int kk = 0; kk < 8; kk++) {
            float4 a0 = *(const float4*)&As[buf][kk][ty * 4];
            float4 a1 = *(const float4*)&As[buf][kk][ty * 4 + 64];
            float4 b0 = *(const float4*)&Bs[buf][kk][tx * 4];
            float4 b1 = *(const float4*)&Bs[buf][kk][tx * 4 + 64];
            float af[8] = {a0.x, a0.y, a0.z, a0.w, a1.x, a1.y, a1.z, a1.w};
            float bf[8] = {b0.x, b0.y, b0.z, b0.w, b1.x, b1.y, b1.z, b1.w};
#pragma unroll
            for (int i = 0; i < 8; i++)
#pragma unroll
                for (int j = 0; j < 8; j++)
                    acc[i][j] += af[i] * bf[j];
        }
        if (t + 1 < nt) { STORE_A(buf ^ 1); STORE_B(buf ^ 1); }
        __syncthreads();
    }

    // ---- epilogue ----
#pragma unroll
    for (int ih = 0; ih < 2; ih++) {
#pragma unroll
        for (int i = 0; i < 4; i++) {
            int m = m0 + ty * 4 + i + ih * 64;
            if (m >= M) continue;
            float bi = bias ? bias[m] : 0.0f;
#pragma unroll
            for (int jh = 0; jh < 2; jh++) {
#pragma unroll
                for (int j = 0; j < 4; j++) {
                    int n = n0 + tx * 4 + j + jh * 64;
                    if (n >= N) continue;
                    float v = acc[ih * 4 + i][jh * 4 + j];
                    if (MODE != 9 && scale) v *= scb[n];
                    v += bi;
                    v = fmaxf(v, 0.0f);
                    Cb[(size_t)m * cStride + n] = v;
                }
            }
        }
    }
#undef LOAD_A
#undef STORE_A
#undef LOAD_B
#undef STORE_B
}

// ---------------- per-column L2 norm of corr -> scale = mask / norm ----------------
__global__ void norm_k() {
    int idx = blockIdx.x * blockDim.x + threadIdx.x;
    if (idx >= BATCH * HW) return;
    int b = idx / HW, q = idx % HW;
    const float* base = g_corr + (size_t)b * HW * HW + q;
    float s0 = 0.f, s1 = 0.f, s2 = 0.f, s3 = 0.f;
    for (int p = 0; p + 4 <= HW; p += 4) {
        float v0 = base[(size_t)(p    ) * HW];
        float v1 = base[(size_t)(p + 1) * HW];
        float v2 = base[(size_t)(p + 2) * HW];
        float v3 = base[(size_t)(p + 3) * HW];
        s0 += v0 * v0; s1 += v1 * v1; s2 += v2 * v2; s3 += v3 * v3;
    }
    float s = (s0 + s1) + (s2 + s3);
    g_scale[idx] = g_mpool[idx] / sqrtf(s);
}

// ---------------- batchnorm stats (training-mode, biased var) ----------------
__global__ void bnstat_k() {
    const int ch  = blockIdx.x;
    const int tid = threadIdx.x;
    const int NEL = BATCH * HW;
    double s = 0.0, ss = 0.0;
    for (int i = tid; i < NEL; i += blockDim.x) {
        int b = i / HW, q = i % HW;
        float v = g_y[(size_t)b * 512 * HW + (size_t)ch * HW + q];
        s  += (double)v;
        ss += (double)v * (double)v;
    }
    __shared__ double sh[256];
    __shared__ double sh2[256];
    sh[tid] = s; sh2[tid] = ss;
    __syncthreads();
    for (int st = 128; st > 0; st >>= 1) {
        if (tid < st) { sh[tid] += sh[tid + st]; sh2[tid] += sh2[tid + st]; }
        __syncthreads();
    }
    if (tid == 0) {
        double mean = sh[0] / NEL;
        double var  = sh2[0] / NEL - mean * mean;
        g_mean[ch] = (float)mean;
        g_inv[ch]  = (float)(1.0 / sqrt(var + 1e-5));
    }
}

__global__ void bnapply_k(const float* __restrict__ gamma,
                          const float* __restrict__ beta,
                          float* __restrict__ out) {
    int idx = blockIdx.x * blockDim.x + threadIdx.x;
    if (idx >= BATCH * 512 * HW) return;
    int ch = (idx / HW) % 512;
    out[idx] = gamma[ch] * (g_y[idx] - g_mean[ch]) * g_inv[ch] + beta[ch];
}

// ---------------- launch ----------------
static float* sym_addr(const void* symbol) {
    void* p = nullptr;
    cudaGetSymbolAddress(&p, symbol);
    return (float*)p;
}

extern "C" void kernel_launch(void* const* d_in, const int* in_sizes, int n_in,
                              void* d_out, int out_size) {
    const float* feature1 = (const float*)d_in[0];
    const float* feature2 = (const float*)d_in[1];
    const float* mask     = (const float*)d_in[2];
    const float* W1  = (const float*)d_in[3];
    const float* b1  = (const float*)d_in[4];
    const float* W2a = (const float*)d_in[5];
    const float* b2a = (const float*)d_in[6];
    const float* W2b = (const float*)d_in[7];
    const float* b2b = (const float*)d_in[8];
    const float* W3a = (const float*)d_in[9];
    const float* b3a = (const float*)d_in[10];
    const float* W3b = (const float*)d_in[11];
    const float* b3b = (const float*)d_in[12];
    const float* W4  = (const float*)d_in[13];
    const float* b4  = (const float*)d_in[14];
    const float* gamma = (const float*)d_in[15];
    const float* beta  = (const float*)d_in[16];
    float* out = (float*)d_out;

    float* f1r  = sym_addr(g_f1r);
    float* f2r  = sym_addr(g_f2r);
    float* corr = sym_addr(g_corr);
    float* scal = sym_addr(g_scale);
    float* y2a  = sym_addr(g_y2a);
    float* y3a  = sym_addr(g_y3a);
    float* ybuf = sym_addr(g_y);

    // 1) resize both features
    {
        int total = 2 * BATCH * CIN * HW;
        resize_k<<<(total + 255) / 256, 256>>>(feature1, feature2);
    }
    // 2) mask maxpool
    mpool_k<<<(BATCH * HW + 255) / 256, 256>>>(mask);

    // 3) correlation GEMM: corr[b][p][q] = relu(sum_c f1r[b][c][p] * f2r[b][c][q])
    {
        dim3 grid(7, 7, BATCH);
        gemm_k<0, false><<<grid, 256>>>(f1r, f2r, corr,
                                        HW, HW, CIN,
                                        (long)CIN * HW, (long)CIN * HW, (long)HW * HW,
                                        HW, 1, nullptr, nullptr, HW);
    }
    // 4) column L2 norm -> scale
    norm_k<<<(BATCH * HW + 255) / 256, 256>>>();

    // 5-8) 1x1 conv branches (normalization scale folded into epilogue / loader)
    {
        dim3 g1(7, 1, BATCH);   // W1: 128 out -> y channels [0,128)
        gemm_k<0, true><<<g1, 256>>>(W1, corr, ybuf,
                                     128, HW, HW,
                                     0L, (long)HW * HW, (long)512 * HW,
                                     1, HW, scal, b1, HW);
        dim3 g2(7, 2, BATCH);   // W2a: 192 out -> y2a
        gemm_k<0, true><<<g2, 256>>>(W2a, corr, y2a,
                                     192, HW, HW,
                                     0L, (long)HW * HW, (long)192 * HW,
                                     1, HW, scal, b2a, HW);
        dim3 g3(7, 1, BATCH);   // W3a: 32 out -> y3a
        gemm_k<0, true><<<g3, 256>>>(W3a, corr, y3a,
                                     32, HW, HW,
                                     0L, (long)HW * HW, (long)32 * HW,
                                     1, HW, scal, b3a, HW);
        dim3 g4(7, 1, BATCH);   // W4 on 3x3-maxpooled scaled corr (fused loader)
        gemm_k<9, true><<<g4, 256>>>(W4, corr, ybuf + (size_t)448 * HW,
                                     64, HW, HW,
                                     0L, (long)HW * HW, (long)512 * HW,
                                     1, HW, scal, b4, HW);
    }
    // 9) 3x3 conv 192->256 (implicit GEMM) -> y channels [128,384)
    {
        dim3 g(7, 2, BATCH);
        gemm_k<3, true><<<g, 256>>>(W2b, y2a, ybuf + (size_t)128 * HW,
                                    256, HW, 192 * 9,
                                    0L, (long)192 * HW, (long)512 * HW,
                                    1, 192 * 9, nullptr, b2b, HW);
    }
    // 10) 5x5 conv 32->64 (implicit GEMM) -> y channels [384,448)
    {
        dim3 g(7, 1, BATCH);
        gemm_k<5, true><<<g, 256>>>(W3b, y3a, ybuf + (size_t)384 * HW,
                                    64, HW, 32 * 25,
                                    0L, (long)32 * HW, (long)512 * HW,
                                    1, 32 * 25, nullptr, b3b, HW);
    }
    // 11) batchnorm stats + apply
    bnstat_k<<<512, 256>>>();
    {
        int total = BATCH * 512 * HW;
        bnapply_k<<<(total + 255) / 256, 256>>>(gamma, beta, out);
    }
}

// round 4
// speedup vs baseline: 1.0761x; 1.0761x over previous
#include <cuda_runtime.h>
#include <math.h>

#define BATCH 32
#define CIN   256
#define OHW   28
#define HW    784          // 28*28
#define IH    56
#define IHW   3136         // 56*56
#define MFUSE 352          // 128 + 192 + 32 stacked branch-weight rows

// ---------------- scratch (static device arrays; no cudaMalloc) ----------------
__device__ float g_f1r [BATCH * CIN * HW];          // resized feature1  [b][c][q]
__device__ float g_f2r [BATCH * CIN * HW];          // resized feature2  [b][c][q]
__device__ float g_mpool[BATCH * HW];               // maxpooled mask    [b][q]
__device__ float g_scale[BATCH * HW];               // mask/||corr||     [b][q]
__device__ float g_corr [(size_t)BATCH * HW * HW];  // relu(corr)        [b][p][q]
__device__ float g_y2a  [BATCH * 192 * HW];
__device__ float g_y3a  [BATCH *  32 * HW];
__device__ float g_y    [BATCH * 512 * HW];         // concat buffer
__device__ float g_mean [512];
__device__ float g_inv  [512];
__device__ float g_Wpk  [MFUSE * HW];               // stacked W1|W2a|W3a
__device__ float g_bpk  [MFUSE];

// ---------------- bilinear resize 56->28, align_corners=True ----------------
__global__ void resize_k(const float* __restrict__ f1, const float* __restrict__ f2) {
    int idx = blockIdx.x * blockDim.x + threadIdx.x;
    const int total = BATCH * CIN * HW;
    if (idx >= 2 * total) return;
    const float* src = (idx < total) ? f1 : f2;
    float* dst       = (idx < total) ? g_f1r : g_f2r;
    int i  = (idx < total) ? idx : idx - total;
    int q  = i % HW;
    int bc = i / HW;
    int oy = q / OHW, ox = q % OHW;
    const float step = 55.0f / 27.0f;
    float fy = oy * step, fx = ox * step;
    int y0 = (int)floorf(fy); if (y0 > IH - 1) y0 = IH - 1;
    int x0 = (int)floorf(fx); if (x0 > IH - 1) x0 = IH - 1;
    int y1 = min(y0 + 1, IH - 1);
    int x1 = min(x0 + 1, IH - 1);
    float wy = fy - (float)y0;
    float wx = fx - (float)x0;
    const float* p = src + (size_t)bc * IHW;
    float v00 = p[y0 * IH + x0], v01 = p[y0 * IH + x1];
    float v10 = p[y1 * IH + x0], v11 = p[y1 * IH + x1];
    float r0 = v00 * (1.0f - wy) + v10 * wy;
    float r1 = v01 * (1.0f - wy) + v11 * wy;
    dst[i] = r0 * (1.0f - wx) + r1 * wx;
}

// ---------------- mask maxpool 2x2 s2 ----------------
__global__ void mpool_k(const float* __restrict__ mask) {
    int idx = blockIdx.x * blockDim.x + threadIdx.x;
    if (idx >= BATCH * HW) return;
    int b = idx / HW, q = idx % HW;
    int y = q / OHW, x = q % OHW;
    const float* p = mask + (size_t)b * IHW;
    float m0 = p[(2*y)   * IH + 2*x], m1 = p[(2*y)   * IH + 2*x + 1];
    float m2 = p[(2*y+1) * IH + 2*x], m3 = p[(2*y+1) * IH + 2*x + 1];
    g_mpool[idx] = fmaxf(fmaxf(m0, m1), fmaxf(m2, m3));
}

// ---------------- pack branch weights into one stacked matrix ----------------
__global__ void pack_k(const float* __restrict__ W1,  const float* __restrict__ b1,
                       const float* __restrict__ W2a, const float* __restrict__ b2a,
                       const float* __restrict__ W3a, const float* __restrict__ b3a) {
    int idx = blockIdx.x * blockDim.x + threadIdx.x;
    if (idx < MFUSE * HW) {
        int m = idx / HW, k = idx % HW;
        float v;
        if (m < 128)      v = W1 [(size_t)m * HW + k];
        else if (m < 320) v = W2a[(size_t)(m - 128) * HW + k];
        else              v = W3a[(size_t)(m - 320) * HW + k];
        g_Wpk[idx] = v;
    }
    if (idx < MFUSE) {
        float v;
        if (idx < 128)      v = b1 [idx];
        else if (idx < 320) v = b2a[idx - 128];
        else                v = b3a[idx - 320];
        g_bpk[idx] = v;
    }
}

// =====================================================================
// 128x128x8 double-buffered SGEMM, 256 threads, 8x8 micro-tile, FFMA2 core.
// C[b][m][n] = relu( epiScale?[b][n] * (sum_k A.B) + bias?[m] )
// MODE: 0 = plain B[k][n] (row stride N)
//       3/5 = conv im2col decode (pad = MODE/2) from B[c][28][28]
//       9 = B[k][n] = max over 3x3 nbhd of corr[k][q']*scale[q'] (W4 branch)
// WA: true -> A is weights [m][k]; false -> A[k][m]
// ROUTE: true -> A = g_Wpk, bias = g_bpk, outputs routed per m to y/y2a/y3a
// =====================================================================
template <int MODE, bool WA, bool ROUTE>
__global__ __launch_bounds__(256, 2)
void gemm_k(const float* __restrict__ A, const float* __restrict__ Bm,
            float* __restrict__ C,
            int M, int N, int K,
            long aB, long bB, long cB,
            int sAk, int sAm,
            const float* __restrict__ scale,
            const float* __restrict__ bias,
            int cStride)
{
    const int b = blockIdx.z;
    const float* Ab = ROUTE ? g_Wpk : (A + (size_t)b * aB);
    const float* Bb = Bm + (size_t)b * bB;
    float*       Cb = C  + (size_t)b * cB;
    const float* scb = scale ? scale + (size_t)b * HW : (const float*)0;

    const int m0 = blockIdx.y * 128;
    const int n0 = blockIdx.x * 128;

    __shared__ __align__(16) float As[2][8][128];
    __shared__ __align__(16) float Bs[2][8][128];

    const int tid = threadIdx.x;
    const int tx  = tid & 15;
    const int ty  = tid >> 4;

    const int a_k  = tid >> 5;
    const int a_m4 = (tid & 31) * 4;
    const int aw_m = tid >> 1;
    const int aw_k = (tid & 1) * 4;
    const int b_k  = tid >> 5;
    const int b_n4 = (tid & 31) * 4;

    float4 avr, bvr;
    const float4 f4z = make_float4(0.f, 0.f, 0.f, 0.f);

#define LOAD_A(K0)                                                              \
    {                                                                           \
        avr = f4z;                                                              \
        if (WA) {                                                               \
            if (m0 + aw_m < M)                                                  \
                avr = *(const float4*)&Ab[(size_t)(m0 + aw_m) * sAm + (K0) + aw_k]; \
        } else {                                                                \
            if (m0 + a_m4 < M)                                                  \
                avr = *(const float4*)&Ab[(size_t)((K0) + a_k) * sAk + m0 + a_m4]; \
        }                                                                       \
    }

#define STORE_A(BUF)                                                            \
    {                                                                           \
        if (WA) {                                                               \
            As[BUF][aw_k + 0][aw_m] = avr.x;                                    \
            As[BUF][aw_k + 1][aw_m] = avr.y;                                    \
            As[BUF][aw_k + 2][aw_m] = avr.z;                                    \
            As[BUF][aw_k + 3][aw_m] = avr.w;                                    \
        } else {                                                                \
            *(float4*)&As[BUF][a_k][a_m4] = avr;                                \
        }                                                                       \
    }

#define LOAD_B(K0)                                                              \
    {                                                                           \
        if (MODE == 0) {                                                        \
            bvr = f4z;                                                          \
            if (n0 + b_n4 < N)                                                  \
                bvr = *(const float4*)&Bb[(size_t)((K0) + b_k) * N + n0 + b_n4];\
        } else if (MODE == 9) {                                                 \
            const int gk = (K0) + b_k;                                          \
            const float* row = Bb + (size_t)gk * HW;                            \
            float vv[4];                                                        \
            _Pragma("unroll")                                                   \
            for (int j = 0; j < 4; j++) {                                       \
                int gn = n0 + b_n4 + j;                                         \
                float mx = 0.0f;                                                \
                if (gn < N) {                                                   \
                    int y = gn / OHW, x = gn % OHW;                             \
                    mx = -INFINITY;                                             \
                    _Pragma("unroll")                                           \
                    for (int dy = -1; dy <= 1; dy++) {                          \
                        int iy = y + dy;                                        \
                        if (iy < 0 || iy >= OHW) continue;                      \
                        _Pragma("unroll")                                       \
                        for (int dx = -1; dx <= 1; dx++) {                      \
                            int ix = x + dx;                                    \
                            if (ix < 0 || ix >= OHW) continue;                  \
                            int qq = iy * OHW + ix;                             \
                            mx = fmaxf(mx, row[qq] * scb[qq]);                  \
                        }                                                       \
                    }                                                           \
                }                                                               \
                vv[j] = mx;                                                     \
            }                                                                   \
            bvr = make_float4(vv[0], vv[1], vv[2], vv[3]);                      \
        } else {                                                                \
            const int kk2 = MODE * MODE;                                        \
            const int pad = MODE / 2;                                           \
            const int gk = (K0) + b_k;                                          \
            const int c  = gk / kk2;                                            \
            const int r  = gk % kk2;                                            \
            const int ky = r / MODE, kx = r % MODE;                             \
            float vv[4];                                                        \
            _Pragma("unroll")                                                   \
            for (int j = 0; j < 4; j++) {                                       \
                int gn = n0 + b_n4 + j;                                         \
                float v = 0.0f;                                                 \
                if (gn < N) {                                                   \
                    int y = gn / OHW + ky - pad;                                \
                    int x = gn % OHW + kx - pad;                                \
                    if (y >= 0 && y < OHW && x >= 0 && x < OHW)                 \
                        v = Bb[c * HW + y * OHW + x];                           \
                }                                                               \
                vv[j] = v;                                                      \
            }                                                                   \
            bvr = make_float4(vv[0], vv[1], vv[2], vv[3]);                      \
        }                                                                       \
    }

#define STORE_B(BUF) { *(float4*)&Bs[BUF][b_k][b_n4] = bvr; }

    // packed f32x2 accumulators: acc2[i][jp] holds output floats
    // (jp<2) -> n = tx*4 + jp*2 + {0,1};  (jp>=2) -> n = 64 + tx*4 + (jp-2)*2 + {0,1}
    unsigned long long acc2[8][4];
#pragma unroll
    for (int i = 0; i < 8; i++)
#pragma unroll
        for (int j = 0; j < 4; j++) acc2[i][j] = 0ULL;

    const int nt = K >> 3;

    LOAD_A(0); LOAD_B(0);
    STORE_A(0); STORE_B(0);
    __syncthreads();

    for (int t = 0; t < nt; t++) {
        const int buf = t & 1;
        if (t + 1 < nt) { LOAD_A((t + 1) * 8); LOAD_B((t + 1) * 8); }
#pragma unroll
        for (int kk = 0; kk < 8; kk++) {
            float4 a0 = *(const float4*)&As[buf][kk][ty * 4];
            float4 a1 = *(const float4*)&As[buf][kk][ty * 4 + 64];
            ulonglong2 bq0 = *(const ulonglong2*)&Bs[buf][kk][tx * 4];
            ulonglong2 bq1 = *(const ulonglong2*)&Bs[buf][kk][tx * 4 + 64];
            unsigned long long bp[4] = {bq0.x, bq0.y, bq1.x, bq1.y};
            float af[8] = {a0.x, a0.y, a0.z, a0.w, a1.x, a1.y, a1.z, a1.w};
#pragma unroll
            for (int i = 0; i < 8; i++) {
                unsigned int au = __float_as_uint(af[i]);
                unsigned long long a2;
                asm("mov.b64 %0, {%1, %1};" : "=l"(a2) : "r"(au));
#pragma unroll
                for (int j = 0; j < 4; j++)
                    asm("fma.rn.f32x2 %0, %1, %2, %3;"
                        : "=l"(acc2[i][j])
                        : "l"(a2), "l"(bp[j]), "l"(acc2[i][j]));
            }
        }
        if (t + 1 < nt) { STORE_A(buf ^ 1); STORE_B(buf ^ 1); }
        __syncthreads();
    }

    // ---- epilogue ----
#pragma unroll
    for (int ih = 0; ih < 2; ih++) {
#pragma unroll
        for (int i = 0; i < 4; i++) {
            int m = m0 + ty * 4 + i + ih * 64;
            if (m >= M) continue;
            float bi;
            float* outp;
            if (ROUTE) {
                bi = g_bpk[m];
                if (m < 128)      outp = g_y   + (size_t)b * 512 * HW + (size_t)m * HW;
                else if (m < 320) outp = g_y2a + (size_t)b * 192 * HW + (size_t)(m - 128) * HW;
                else              outp = g_y3a + (size_t)b *  32 * HW + (size_t)(m - 320) * HW;
            } else {
                bi = bias ? bias[m] : 0.0f;
                outp = Cb + (size_t)m * cStride;
            }
#pragma unroll
            for (int jp = 0; jp < 4; jp++) {
                unsigned int lu, hu;
                asm("mov.b64 {%0, %1}, %2;" : "=r"(lu), "=r"(hu)
                    : "l"(acc2[ih * 4 + i][jp]));
                float v0 = __uint_as_float(lu);
                float v1 = __uint_as_float(hu);
                int nb = n0 + tx * 4 + (jp & 1) * 2 + (jp >> 1) * 64;
                if (nb < N) {
                    float v = v0;
                    if (MODE != 9 && scale) v *= scb[nb];
                    v = fmaxf(v + bi, 0.0f);
                    outp[nb] = v;
                }
                if (nb + 1 < N) {
                    float v = v1;
                    if (MODE != 9 && scale) v *= scb[nb + 1];
                    v = fmaxf(v + bi, 0.0f);
                    outp[nb + 1] = v;
                }
            }
        }
    }
#undef LOAD_A
#undef STORE_A
#undef LOAD_B
#undef STORE_B
}

// ---------------- per-column L2 norm of corr -> scale = mask / norm ----------------
__global__ void norm_k() {
    int idx = blockIdx.x * blockDim.x + threadIdx.x;
    if (idx >= BATCH * HW) return;
    int b = idx / HW, q = idx % HW;
    const float* base = g_corr + (size_t)b * HW * HW + q;
    float s0 = 0.f, s1 = 0.f, s2 = 0.f, s3 = 0.f;
    for (int p = 0; p + 4 <= HW; p += 4) {
        float v0 = base[(size_t)(p    ) * HW];
        float v1 = base[(size_t)(p + 1) * HW];
        float v2 = base[(size_t)(p + 2) * HW];
        float v3 = base[(size_t)(p + 3) * HW];
        s0 += v0 * v0; s1 += v1 * v1; s2 += v2 * v2; s3 += v3 * v3;
    }
    float s = (s0 + s1) + (s2 + s3);
    g_scale[idx] = g_mpool[idx] / sqrtf(s);
}

// ---------------- batchnorm stats (training-mode, biased var) ----------------
__global__ void bnstat_k() {
    const int ch  = blockIdx.x;
    const int tid = threadIdx.x;
    const int NEL = BATCH * HW;
    double s = 0.0, ss = 0.0;
    for (int i = tid; i < NEL; i += blockDim.x) {
        int b = i / HW, q = i % HW;
        float v = g_y[(size_t)b * 512 * HW + (size_t)ch * HW + q];
        s  += (double)v;
        ss += (double)v * (double)v;
    }
    __shared__ double sh[256];
    __shared__ double sh2[256];
    sh[tid] = s; sh2[tid] = ss;
    __syncthreads();
    for (int st = 128; st > 0; st >>= 1) {
        if (tid < st) { sh[tid] += sh[tid + st]; sh2[tid] += sh2[tid + st]; }
        __syncthreads();
    }
    if (tid == 0) {
        double mean = sh[0] / NEL;
        double var  = sh2[0] / NEL - mean * mean;
        g_mean[ch] = (float)mean;
        g_inv[ch]  = (float)(1.0 / sqrt(var + 1e-5));
    }
}

__global__ void bnapply_k(const float* __restrict__ gamma,
                          const float* __restrict__ beta,
                          float* __restrict__ out) {
    int idx = blockIdx.x * blockDim.x + threadIdx.x;
    if (idx >= BATCH * 512 * HW) return;
    int ch = (idx / HW) % 512;
    out[idx] = gamma[ch] * (g_y[idx] - g_mean[ch]) * g_inv[ch] + beta[ch];
}

// ---------------- launch ----------------
static float* sym_addr(const void* symbol) {
    void* p = nullptr;
    cudaGetSymbolAddress(&p, symbol);
    return (float*)p;
}

extern "C" void kernel_launch(void* const* d_in, const int* in_sizes, int n_in,
                              void* d_out, int out_size) {
    const float* feature1 = (const float*)d_in[0];
    const float* feature2 = (const float*)d_in[1];
    const float* mask     = (const float*)d_in[2];
    const float* W1  = (const float*)d_in[3];
    const float* b1  = (const float*)d_in[4];
    const float* W2a = (const float*)d_in[5];
    const float* b2a = (const float*)d_in[6];
    const float* W2b = (const float*)d_in[7];
    const float* b2b = (const float*)d_in[8];
    const float* W3a = (const float*)d_in[9];
    const float* b3a = (const float*)d_in[10];
    const float* W3b = (const float*)d_in[11];
    const float* b3b = (const float*)d_in[12];
    const float* W4  = (const float*)d_in[13];
    const float* b4  = (const float*)d_in[14];
    const float* gamma = (const float*)d_in[15];
    const float* beta  = (const float*)d_in[16];
    float* out = (float*)d_out;

    float* f1r  = sym_addr(g_f1r);
    float* f2r  = sym_addr(g_f2r);
    float* corr = sym_addr(g_corr);
    float* scal = sym_addr(g_scale);
    float* y2a  = sym_addr(g_y2a);
    float* y3a  = sym_addr(g_y3a);
    float* ybuf = sym_addr(g_y);

    // 1) resize both features
    {
        int total = 2 * BATCH * CIN * HW;
        resize_k<<<(total + 255) / 256, 256>>>(feature1, feature2);
    }
    // 2) mask maxpool + weight packing
    mpool_k<<<(BATCH * HW + 255) / 256, 256>>>(mask);
    pack_k<<<(MFUSE * HW + 255) / 256, 256>>>(W1, b1, W2a, b2a, W3a, b3a);

    // 3) correlation GEMM: corr[b][p][q] = relu(sum_c f1r[b][c][p] * f2r[b][c][q])
    {
        dim3 grid(7, 7, BATCH);
        gemm_k<0, false, false><<<grid, 256>>>(f1r, f2r, corr,
                                               HW, HW, CIN,
                                               (long)CIN * HW, (long)CIN * HW, (long)HW * HW,
                                               HW, 1, nullptr, nullptr, HW);
    }
    // 4) column L2 norm -> scale
    norm_k<<<(BATCH * HW + 255) / 256, 256>>>();

    // 5) fused branch GEMM: W1|W2a|W3a (M=352), scale folded in epilogue
    {
        dim3 g(7, 3, BATCH);
        gemm_k<0, true, true><<<g, 256>>>(nullptr, corr, nullptr,
                                          MFUSE, HW, HW,
                                          0L, (long)HW * HW, 0L,
                                          1, HW, scal, nullptr, HW);
    }
    // 6) W4 on 3x3-maxpooled scaled corr (pool fused in B loader)
    {
        dim3 g(7, 1, BATCH);
        gemm_k<9, true, false><<<g, 256>>>(W4, corr, ybuf + (size_t)448 * HW,
                                           64, HW, HW,
                                           0L, (long)HW * HW, (long)512 * HW,
                                           1, HW, scal, b4, HW);
    }
    // 7) 3x3 conv 192->256 (implicit GEMM) -> y channels [128,384)
    {
        dim3 g(7, 2, BATCH);
        gemm_k<3, true, false><<<g, 256>>>(W2b, y2a, ybuf + (size_t)128 * HW,
                                           256, HW, 192 * 9,
                                           0L, (long)192 * HW, (long)512 * HW,
                                           1, 192 * 9, nullptr, b2b, HW);
    }
    // 8) 5x5 conv 32->64 (implicit GEMM) -> y channels [384,448)
    {
        dim3 g(7, 1, BATCH);
        gemm_k<5, true, false><<<g, 256>>>(W3b, y3a, ybuf + (size_t)384 * HW,
                                           64, HW, 32 * 25,
                                           0L, (long)32 * HW, (long)512 * HW,
                                           1, 32 * 25, nullptr, b3b, HW);
    }
    // 9) batchnorm stats + apply
    bnstat_k<<<512, 256>>>();
    {
        int total = BATCH * 512 * HW;
        bnapply_k<<<(total + 255) / 256, 256>>>(gamma, beta, out);
    }
}